// round 2
// baseline (speedup 1.0000x reference)
#include <cuda_runtime.h>

// Shapes fixed by the problem
#define B_DIM 512
#define T_DIM 400
#define V_DIM 32000
#define ENC_DIM 1024
#define HID_DIM 1024
#define EMB_DIM 512

#define SLICES 4                       // column slices per row
#define SLICE_F (V_DIM / SLICES)       // 8000 floats per slice
#define SLICE_F4 (SLICE_F / 4)         // 2000 float4 per slice
#define NT2 256                        // threads in main kernel
#define BATCH 8                        // float4 per thread (7 full + 1 partial)

__device__ float g_pgen[B_DIM];

// ---------------------------------------------------------------------------
// Kernel 1: per-row p_gen = sigmoid(context.w_c + state.w_s + emb.w_y + b)
// ---------------------------------------------------------------------------
__global__ __launch_bounds__(256)
void pgen_kernel(
    const float* __restrict__ context,  // [B, ENC]
    const float* __restrict__ state,    // [B, HID]
    const float* __restrict__ emb,      // [B, EMB]
    const float* __restrict__ w_c,      // [ENC]
    const float* __restrict__ w_s,      // [HID]
    const float* __restrict__ w_y,      // [EMB]
    const float* __restrict__ b_p)      // [1]
{
    const int row = blockIdx.x;
    const int tid = threadIdx.x;

    float acc = 0.0f;

    // ENC: 256 float4, one per thread
    {
        const float4 a = reinterpret_cast<const float4*>(context + (size_t)row * ENC_DIM)[tid];
        const float4 w = reinterpret_cast<const float4*>(w_c)[tid];
        acc += a.x * w.x + a.y * w.y + a.z * w.z + a.w * w.w;
    }
    // HID: 256 float4, one per thread
    {
        const float4 a = reinterpret_cast<const float4*>(state + (size_t)row * HID_DIM)[tid];
        const float4 w = reinterpret_cast<const float4*>(w_s)[tid];
        acc += a.x * w.x + a.y * w.y + a.z * w.z + a.w * w.w;
    }
    // EMB: 128 float4, first half of threads
    if (tid < EMB_DIM / 4) {
        const float4 a = reinterpret_cast<const float4*>(emb + (size_t)row * EMB_DIM)[tid];
        const float4 w = reinterpret_cast<const float4*>(w_y)[tid];
        acc += a.x * w.x + a.y * w.y + a.z * w.z + a.w * w.w;
    }

    // warp reduce
    #pragma unroll
    for (int off = 16; off > 0; off >>= 1)
        acc += __shfl_down_sync(0xffffffffu, acc, off);

    __shared__ float s_partial[8];
    const int lane = tid & 31;
    const int wid  = tid >> 5;
    if (lane == 0) s_partial[wid] = acc;
    __syncthreads();
    if (tid == 0) {
        float total = 0.0f;
        #pragma unroll
        for (int i = 0; i < 8; i++) total += s_partial[i];
        total += b_p[0];
        g_pgen[row] = 1.0f / (1.0f + __expf(-total));
    }
}

// ---------------------------------------------------------------------------
// Kernel 2: out = p_gen * vocab_dist, then masked scatter-add of
//           (1-p_gen)*attn at src_ids.  Each CTA owns one (row, slice) and
//           handles only the scatter targets landing inside its slice, so
//           the intra-CTA barrier fully orders store -> atomic.
// ---------------------------------------------------------------------------
__global__ __launch_bounds__(NT2)
void scale_scatter_kernel(
    const float* __restrict__ vocab_dist,   // [B, V]
    const float* __restrict__ attn_dist,    // [B, T]
    const int*   __restrict__ src_ids,      // [B, T]
    const int*   __restrict__ vocab_size_p, // scalar
    float*       __restrict__ out)          // [B, V]
{
    const int bid   = blockIdx.x;
    const int row   = bid >> 2;      // SLICES == 4
    const int slice = bid & 3;
    const int tid   = threadIdx.x;

    const float pg = g_pgen[row];
    const float pc = 1.0f - pg;

    const float4* v4 = reinterpret_cast<const float4*>(vocab_dist + (size_t)row * V_DIM) + slice * SLICE_F4;
    float4*       o4 = reinterpret_cast<float4*>(out + (size_t)row * V_DIM) + slice * SLICE_F4;

    // ---- Phase A: front-batched scale.  2000 float4 / 256 threads:
    //      7 full batches + partial batch (tid < 208).
    float4 r[BATCH];
    #pragma unroll
    for (int k = 0; k < BATCH - 1; k++)
        r[k] = v4[tid + k * NT2];
    const bool has_last = tid < (SLICE_F4 - (BATCH - 1) * NT2);   // tid < 208
    if (has_last)
        r[BATCH - 1] = v4[tid + (BATCH - 1) * NT2];

    #pragma unroll
    for (int k = 0; k < BATCH - 1; k++) {
        float4 x = r[k];
        x.x *= pg; x.y *= pg; x.z *= pg; x.w *= pg;
        __stcs(o4 + tid + k * NT2, x);   // evict-first: keep vocab_dist L2-resident
    }
    if (has_last) {
        float4 x = r[BATCH - 1];
        x.x *= pg; x.y *= pg; x.z *= pg; x.w *= pg;
        __stcs(o4 + tid + (BATCH - 1) * NT2, x);
    }

    // Block-scope global ordering: this CTA's stores are visible to this
    // CTA's atomics after the barrier; scatter below targets ONLY this slice.
    __syncthreads();

    // ---- Phase B: masked scatter-add restricted to this slice's columns.
    const int vsz = *vocab_size_p;
    const int lo  = slice * SLICE_F;
    const int hi  = lo + SLICE_F;
    const int*   ids = src_ids  + (size_t)row * T_DIM;
    const float* at  = attn_dist + (size_t)row * T_DIM;

    #pragma unroll
    for (int t = tid; t < T_DIM; t += NT2) {
        const int id = ids[t];
        if (id < vsz && id >= lo && id < hi) {
            atomicAdd(out + (size_t)row * V_DIM + id, pc * at[t]);
        }
    }
}

extern "C" void kernel_launch(void* const* d_in, const int* in_sizes, int n_in,
                              void* d_out, int out_size) {
    const float* vocab_dist = (const float*)d_in[0];
    const float* attn_dist  = (const float*)d_in[1];
    const float* context    = (const float*)d_in[2];
    const float* state      = (const float*)d_in[3];
    const float* emb        = (const float*)d_in[4];
    const int*   src_ids    = (const int*)d_in[5];
    const int*   vocab_size = (const int*)d_in[6];
    const float* w_c        = (const float*)d_in[7];
    const float* w_s        = (const float*)d_in[8];
    const float* w_y        = (const float*)d_in[9];
    const float* b          = (const float*)d_in[10];
    float*       out        = (float*)d_out;

    pgen_kernel<<<B_DIM, 256>>>(context, state, emb, w_c, w_s, w_y, b);
    scale_scatter_kernel<<<B_DIM * SLICES, NT2>>>(vocab_dist, attn_dist, src_ids, vocab_size, out);
}